// round 7
// baseline (speedup 1.0000x reference)
#include <cuda_runtime.h>
#include <cstdint>

#define NB 8
#define NPTS 16384
#define NS 1024
#define NK 32
#define ND 64
#define NC0 67
#define MTOT (NB*NS*NK)
#define BN_EPS 1e-5f
typedef unsigned long long ull;

__device__ float g_X0[(size_t)NC0*MTOT];
__device__ float g_A [(size_t)64 *MTOT];
__device__ float g_Bf[(size_t)64 *MTOT];
__device__ float g_Y3[(size_t)128*MTOT];
__device__ float g_newxyz[NB*NS*3];
__device__ int   g_fps[NB*NS];
__device__ float g_sum[3*128];
__device__ float g_ssq[3*128];

struct Far0 { int v[NB]; };
__device__ __forceinline__ ull umax64(ull a, ull b){ return a>b?a:b; }
__device__ __forceinline__ ull umin64(ull a, ull b){ return a<b?a:b; }

// ---------------- FPS: one block/batch ----------------
__global__ __launch_bounds__(1024,1)
void fps_kernel(const float* __restrict__ xyz, int* __restrict__ fps_idx,
                float* __restrict__ newxyz, float* __restrict__ out_xyz, Far0 far0)
{
    const int b = blockIdx.x, tid = threadIdx.x;
    const float* xb = xyz + (size_t)b*3*NPTS;
    extern __shared__ char smraw[];
    float2* sxy = (float2*)smraw;
    float*  sz  = (float*)(smraw + (size_t)NPTS*8);
    __shared__ ull warpbest[32];
    __shared__ int s_far;
    for (int i = tid; i < NPTS; i += 1024) {
        sxy[i] = make_float2(xb[i], xb[NPTS+i]);
        sz[i]  = xb[2*NPTS+i];
    }
    __syncthreads();
    float dist[16];
#pragma unroll
    for (int i = 0; i < 16; i++) dist[i] = __int_as_float(0x7f800000);
    int far = far0.v[b];
    for (int s = 0; s < NS; s++) {
        float2 cxy = sxy[far]; float cz = sz[far];
        if (tid == 0) {
            fps_idx[b*NS+s] = far;
            int p = (b*NS+s)*3;
            newxyz[p+0]=cxy.x; newxyz[p+1]=cxy.y; newxyz[p+2]=cz;
            out_xyz[(size_t)b*3*NS + 0*NS + s] = cxy.x;
            out_xyz[(size_t)b*3*NS + 1*NS + s] = cxy.y;
            out_xyz[(size_t)b*3*NS + 2*NS + s] = cz;
        }
        ull best = 0;
#pragma unroll
        for (int i = 0; i < 16; i++) {
            int n = tid + i*1024;
            float2 p = sxy[n]; float pz = sz[n];
            float dx = p.x-cxy.x, dy = p.y-cxy.y, dz = pz-cz;
            // match XLA: no fma contraction
            float d = __fadd_rn(__fadd_rn(__fmul_rn(dx,dx),__fmul_rn(dy,dy)),__fmul_rn(dz,dz));
            float dd = fminf(dist[i], d);
            dist[i] = dd;
            best = umax64(best, ((ull)__float_as_uint(dd)<<32) | (unsigned)(0xFFFFFFFFu-(unsigned)n));
        }
#pragma unroll
        for (int off = 16; off; off >>= 1) best = umax64(best, __shfl_down_sync(~0u, best, off));
        if ((tid&31)==0) warpbest[tid>>5] = best;
        __syncthreads();
        if (tid < 32) {
            ull v = warpbest[tid];
#pragma unroll
            for (int off = 16; off; off >>= 1) v = umax64(v, __shfl_down_sync(~0u, v, off));
            if (tid == 0) s_far = (int)(0xFFFFFFFFu-(unsigned)v);
        }
        __syncthreads();
        far = s_far;
    }
}

// ---------------- kNN radix-select + grouping ----------------
__global__ __launch_bounds__(128,2)
void knn_kernel(const float* __restrict__ xyz, const float* __restrict__ points,
                const float* __restrict__ newxyz, float* __restrict__ X0)
{
    const int blk = blockIdx.x, b = blk >> 10, tid = threadIdx.x;
    const float* xb = xyz + (size_t)b*3*NPTS;
    extern __shared__ char smraw[];
    float* sdist = (float*)smraw;              // 64KB
    int*   hist  = (int*)(smraw + 65536);      // 16KB
    int*   cand  = hist + 4096;                // 8KB
    __shared__ int sel[NK];
    __shared__ int selcnt, candcnt, s_bstar, s_below;
    __shared__ int csum[128];
    __shared__ ull wred[4];
    const float cx = newxyz[blk*3+0], cy = newxyz[blk*3+1], cz = newxyz[blk*3+2];

    for (int i = tid; i < 4096; i += 128) hist[i] = 0;
    if (tid == 0) { selcnt = 0; candcnt = 0; }
    __syncthreads();
    for (int i = 0; i < 128; i++) {
        int n = i*128 + tid;
        float dx = xb[n]-cx, dy = xb[NPTS+n]-cy, dz = xb[2*NPTS+n]-cz;
        float d = dx*dx + dy*dy + dz*dz;
        sdist[n] = d;
        atomicAdd(&hist[__float_as_uint(d)>>20], 1);
    }
    __syncthreads();
    int cs = 0;
    for (int j = 0; j < 32; j++) cs += hist[tid*32+j];
    csum[tid] = cs;
    __syncthreads();
    for (int off = 1; off < 128; off <<= 1) {
        int v = csum[tid];
        int add = (tid >= off) ? csum[tid-off] : 0;
        __syncthreads();
        csum[tid] = v + add;
        __syncthreads();
    }
    int incl = csum[tid], excl = incl - cs;
    if (excl < NK && incl >= NK) {
        int acc = excl, bstar = -1;
        for (int j = 0; j < 32; j++) {
            int h = hist[tid*32+j];
            if (acc + h >= NK) { bstar = tid*32+j; break; }
            acc += h;
        }
        s_bstar = bstar; s_below = acc;
    }
    __syncthreads();
    const int bstar = s_bstar, below = s_below;
    for (int i = 0; i < 128; i++) {
        int n = i*128 + tid;
        int bin = (int)(__float_as_uint(sdist[n])>>20);
        if (bin < bstar)       { int p = atomicAdd(&selcnt,1); sel[p] = n; }
        else if (bin == bstar) { int p = atomicAdd(&candcnt,1); if (p < 2048) cand[p] = n; }
    }
    __syncthreads();
    const int r = NK - below;
    const bool fb = (candcnt > 2048);
    for (int e = 0; e < r; e++) {
        ull best = ~0ull;
        if (!fb) {
            for (int i = tid; i < candcnt; i += 128) {
                int n = cand[i];
                best = umin64(best, ((ull)__float_as_uint(sdist[n])<<32) | (unsigned)n);
            }
        } else {
            for (int i = 0; i < 128; i++) {
                int n = i*128 + tid;
                unsigned u = __float_as_uint(sdist[n]);
                if ((int)(u>>20) == bstar) best = umin64(best, ((ull)u<<32) | (unsigned)n);
            }
        }
#pragma unroll
        for (int off = 16; off; off >>= 1) best = umin64(best, __shfl_down_sync(~0u, best, off));
        if ((tid&31)==0) wred[tid>>5] = best;
        __syncthreads();
        if (tid == 0) {
            best = umin64(umin64(wred[0],wred[1]), umin64(wred[2],wred[3]));
            int n = (int)(unsigned)best;
            sel[below+e] = n;
            sdist[n] = __int_as_float(0x7f800000);
        }
        __syncthreads();
    }
    const size_t mb = (size_t)blk*NK;
    const float* pb = points + (size_t)b*ND*NPTS;
    for (int t = tid; t < NC0*NK; t += 128) {
        int c = t>>5, k = t&31;
        int idx = sel[k];
        float v;
        if (c < 3) {
            float cc = (c==0)?cx:((c==1)?cy:cz);
            v = xb[(size_t)c*NPTS+idx] - cc;
        } else v = pb[(size_t)(c-3)*NPTS+idx];
        X0[(size_t)c*MTOT + mb + k] = v;
    }
}

// ---------------- GEMM 64(o)x128(m) tile ----------------
template <int C>
__global__ __launch_bounds__(256)
void gemm_kernel(const float* __restrict__ X, const float* __restrict__ W,
                 const float* __restrict__ bias, float* __restrict__ Y)
{
    extern __shared__ float smf[];
    float* Ws = smf;           // [C][64]
    float* Xs = smf + C*64;    // [C][128]
    const int m0 = blockIdx.x*128, ob = blockIdx.y*64;
    for (int i = threadIdx.x; i < C*64; i += 256) {
        int o = i&63, c = i>>6;
        Ws[c*64+o] = W[(size_t)(ob+o)*C + c];
    }
    for (int i = threadIdx.x; i < C*128; i += 256) {
        int c = i>>7, j = i&127;
        Xs[c*128+j] = X[(size_t)c*MTOT + m0 + j];
    }
    __syncthreads();
    const int tm = (threadIdx.x&31)*4, to = (threadIdx.x>>5)*8;
    float4 acc[8];
#pragma unroll
    for (int j = 0; j < 8; j++) acc[j] = make_float4(0.f,0.f,0.f,0.f);
#pragma unroll 4
    for (int c = 0; c < C; c++) {
        const float4 xv = *(const float4*)(Xs + c*128 + tm);
        const float4 wa = *(const float4*)(Ws + c*64 + to);
        const float4 wb = *(const float4*)(Ws + c*64 + to + 4);
        const float w[8] = {wa.x,wa.y,wa.z,wa.w,wb.x,wb.y,wb.z,wb.w};
#pragma unroll
        for (int j = 0; j < 8; j++) {
            acc[j].x = fmaf(w[j], xv.x, acc[j].x);
            acc[j].y = fmaf(w[j], xv.y, acc[j].y);
            acc[j].z = fmaf(w[j], xv.z, acc[j].z);
            acc[j].w = fmaf(w[j], xv.w, acc[j].w);
        }
    }
#pragma unroll
    for (int j = 0; j < 8; j++) {
        int row = ob + to + j;
        float bo = bias[row];
        float4 rv = acc[j];
        rv.x += bo; rv.y += bo; rv.z += bo; rv.w += bo;
        *(float4*)(Y + (size_t)row*MTOT + m0 + tm) = rv;
    }
}

// ---------------- BN stats / apply / maxpool ----------------
__global__ void zero_stats_kernel(float* sum, float* ssq)
{
    int i = threadIdx.x;
    if (i < 3*128) { sum[i] = 0.f; ssq[i] = 0.f; }
}

__global__ __launch_bounds__(256)
void stats_kernel(const float* __restrict__ Y, float* __restrict__ sum, float* __restrict__ ssq)
{
    const int o = blockIdx.x >> 5;
    const int chunk = (blockIdx.x & 31) << 13;
    const float* p = Y + (size_t)o*MTOT + chunk;
    float s = 0.f, q = 0.f;
    for (int i = threadIdx.x; i < 8192; i += 256) {
        float v = __ldg(p+i);
        s += v; q += v*v;
    }
#pragma unroll
    for (int off = 16; off; off >>= 1) {
        s += __shfl_down_sync(~0u, s, off);
        q += __shfl_down_sync(~0u, q, off);
    }
    __shared__ float ws[8], wq[8];
    if ((threadIdx.x&31)==0) { ws[threadIdx.x>>5] = s; wq[threadIdx.x>>5] = q; }
    __syncthreads();
    if (threadIdx.x < 8) {
        s = ws[threadIdx.x]; q = wq[threadIdx.x];
#pragma unroll
        for (int off = 4; off; off >>= 1) {
            s += __shfl_down_sync(0xFFu, s, off);
            q += __shfl_down_sync(0xFFu, q, off);
        }
        if (threadIdx.x == 0) { atomicAdd(&sum[o], s); atomicAdd(&ssq[o], q); }
    }
}

__global__ __launch_bounds__(256)
void bn_relu_kernel(float* __restrict__ Y, const float* __restrict__ sum,
                    const float* __restrict__ ssq, const float* __restrict__ gamma,
                    const float* __restrict__ beta)
{
    const int o = blockIdx.x >> 8;
    const int base = (blockIdx.x & 255)*1024 + threadIdx.x*4;
    const float inv = 1.0f/(float)MTOT;
    float mean = sum[o]*inv;
    float var  = ssq[o]*inv - mean*mean;
    float sc = gamma[o]*rsqrtf(var + BN_EPS);
    float sh = beta[o] - sc*mean;
    float4* p = (float4*)(Y + (size_t)o*MTOT + base);
    float4 v = *p;
    v.x = fmaxf(fmaf(sc,v.x,sh),0.f); v.y = fmaxf(fmaf(sc,v.y,sh),0.f);
    v.z = fmaxf(fmaf(sc,v.z,sh),0.f); v.w = fmaxf(fmaf(sc,v.w,sh),0.f);
    *p = v;
}

__global__ __launch_bounds__(256)
void maxpool_kernel(const float* __restrict__ X, float* __restrict__ out)
{
    const int j = blockIdx.x*256 + threadIdx.x;
    const int b = j >> 17, o = (j >> 10) & 127, s = j & 1023;
    const float4* p = (const float4*)(X + (size_t)o*MTOT + ((size_t)(b*NS+s)<<5));
    float m = -__int_as_float(0x7f800000);
#pragma unroll
    for (int i = 0; i < 8; i++) {
        float4 v = p[i];
        m = fmaxf(m, fmaxf(fmaxf(v.x,v.y), fmaxf(v.z,v.w)));
    }
    out[j] = m;
}

// ---------------- host threefry for far0 ----------------
static inline uint32_t rotl32(uint32_t x, int d){ return (x<<d)|(x>>(32-d)); }
static void tf2x32(uint32_t k0, uint32_t k1, uint32_t x0, uint32_t x1,
                   uint32_t* o0, uint32_t* o1)
{
    uint32_t ks[3] = { k0, k1, k0^k1^0x1BD11BDAu };
    x0 += ks[0]; x1 += ks[1];
    static const int R[2][4] = { {13,15,26,6}, {17,29,16,24} };
    for (int g = 0; g < 5; g++) {
        const int* r = R[g&1];
        for (int i = 0; i < 4; i++) { x0 += x1; x1 = rotl32(x1, r[i]); x1 ^= x0; }
        x0 += ks[(g+1)%3];
        x1 += ks[(g+2)%3] + (uint32_t)(g+1);
    }
    *o0 = x0; *o1 = x1;
}
static void compute_far0(int* far)
{
    // jax.random.randint(key(42), (8,), 0, 16384) with threefry_partitionable
    // (default since JAX 0.4.30):
    //   k1, k2 = split(key): subkey_i = block(key, (0, i)) -> key data (o0, o1)
    //   higher_bits from k1, lower_bits from k2
    //   span = 16384 = 2^14 -> multiplier = (2^16 % span)^2 % span = 0
    //   => far0 = lower_bits % span
    //   partitionable random_bits(32, shape (8,)): bits[i] = o0 ^ o1 of
    //   block(k2, (0, i))
    // Fallback (legacy, if this fails ~sqrt(2)): k2 = (o1 of block(key,(0,2)),
    //   o1 of block(key,(1,3))); lower_bits[j] = o0 of block(k2,(j,j+4)) j<4,
    //   lower_bits[4+j] = o1 of block(k2,(j,j+4)).
    uint32_t ka, kb;
    tf2x32(0u, 42u, 0u, 1u, &ka, &kb);       // k2 = second subkey
    for (int i = 0; i < NB; i++) {
        uint32_t o0, o1;
        tf2x32(ka, kb, 0u, (uint32_t)i, &o0, &o1);
        far[i] = (int)((o0 ^ o1) & (NPTS - 1));
    }
}

extern "C" void kernel_launch(void* const* d_in, const int* in_sizes, int n_in,
                              void* d_out, int out_size)
{
    const float* xyz    = (const float*)d_in[0];
    const float* points = (const float*)d_in[1];
    const float* w0 = (const float*)d_in[2];
    const float* b0 = (const float*)d_in[3];
    const float* g0 = (const float*)d_in[4];
    const float* be0= (const float*)d_in[5];
    const float* w1 = (const float*)d_in[6];
    const float* b1 = (const float*)d_in[7];
    const float* g1 = (const float*)d_in[8];
    const float* be1= (const float*)d_in[9];
    const float* w2 = (const float*)d_in[10];
    const float* b2 = (const float*)d_in[11];
    const float* g2 = (const float*)d_in[12];
    const float* be2= (const float*)d_in[13];
    float* out = (float*)d_out;

    Far0 f; compute_far0(f.v);

    float *X0,*A,*Bf,*Y3,*nxyz,*sum,*ssq; int* fps;
    cudaGetSymbolAddress((void**)&X0, g_X0);
    cudaGetSymbolAddress((void**)&A,  g_A);
    cudaGetSymbolAddress((void**)&Bf, g_Bf);
    cudaGetSymbolAddress((void**)&Y3, g_Y3);
    cudaGetSymbolAddress((void**)&nxyz, g_newxyz);
    cudaGetSymbolAddress((void**)&fps, g_fps);
    cudaGetSymbolAddress((void**)&sum, g_sum);
    cudaGetSymbolAddress((void**)&ssq, g_ssq);

    const int FPS_SMEM = NPTS*12;
    const int KNN_SMEM = 65536 + 16384 + 8192;
    const int G67_SMEM = (NC0*64 + NC0*128)*4;
    const int G64_SMEM = (64*64 + 64*128)*4;
    cudaFuncSetAttribute(fps_kernel, cudaFuncAttributeMaxDynamicSharedMemorySize, FPS_SMEM);
    cudaFuncSetAttribute(knn_kernel, cudaFuncAttributeMaxDynamicSharedMemorySize, KNN_SMEM);
    cudaFuncSetAttribute(gemm_kernel<NC0>, cudaFuncAttributeMaxDynamicSharedMemorySize, G67_SMEM);
    cudaFuncSetAttribute(gemm_kernel<64>,  cudaFuncAttributeMaxDynamicSharedMemorySize, G64_SMEM);

    fps_kernel<<<NB, 1024, FPS_SMEM>>>(xyz, fps, nxyz, out, f);
    knn_kernel<<<NB*NS, 128, KNN_SMEM>>>(xyz, points, nxyz, X0);

    zero_stats_kernel<<<1, 512>>>(sum, ssq);

    gemm_kernel<NC0><<<dim3(MTOT/128,1), 256, G67_SMEM>>>(X0, w0, b0, A);
    stats_kernel<<<64*32, 256>>>(A, sum+0, ssq+0);
    bn_relu_kernel<<<64*256, 256>>>(A, sum+0, ssq+0, g0, be0);

    gemm_kernel<64><<<dim3(MTOT/128,1), 256, G64_SMEM>>>(A, w1, b1, Bf);
    stats_kernel<<<64*32, 256>>>(Bf, sum+64, ssq+64);
    bn_relu_kernel<<<64*256, 256>>>(Bf, sum+64, ssq+64, g1, be1);

    gemm_kernel<64><<<dim3(MTOT/128,2), 256, G64_SMEM>>>(Bf, w2, b2, Y3);
    stats_kernel<<<128*32, 256>>>(Y3, sum+128, ssq+128);
    bn_relu_kernel<<<128*256, 256>>>(Y3, sum+128, ssq+128, g2, be2);

    maxpool_kernel<<<(NB*128*NS)/256, 256>>>(Y3, out + NB*3*NS);
}